// round 6
// baseline (speedup 1.0000x reference)
#include <cuda_runtime.h>
#include <stdint.h>

#define NLAYERS 24
#define BATCH   512
#define RDIM    32
#define LQ      256
#define NROWS   (NLAYERS*BATCH*RDIM)   /* 393216 rows of 256 floats */
#define NCHUNKS (NROWS/8)              /* 49152 chunks: 8 rows in, 8x257 out */
#define COPYGRID 888                   /* 148 SMs x 6 blocks, one wave */
#define FULLMASK 0xffffffffu

// ---------------- scratch (static device globals; no allocation) ----------------
__device__ float2 g_wT  [NLAYERS*32*128];  // [l][j][row] -> (w_past, w_h)
__device__ float  g_f1T [NLAYERS*32*128];  // [l][j][k]
__device__ float  g_hcol[NROWS];           // h BEFORE layer l, index = (l*512+b)*32+r

__device__ __forceinline__ float sigf(float v) { return 1.0f / (1.0f + __expf(-v)); }

// ---------------- K0: weight transposes ----------------
__global__ void prep_kernel(const float* __restrict__ conv_w,
                            const float* __restrict__ fc1_w) {
    int idx = blockIdx.x * blockDim.x + threadIdx.x;
    if (idx >= NLAYERS * 32 * 128) return;
    {
        int l = idx / 4096, rem = idx & 4095, row = rem / 32, j = rem & 31;
        float2 v = ((const float2*)conv_w)[idx];
        g_wT[(l * 32 + j) * 128 + row] = v;
    }
    {
        int l = idx / 4096, rem = idx & 4095, j = rem >> 7, k = rem & 127;
        g_f1T[idx] = fc1_w[k * 768 + l * 32 + j];
        (void)l;
    }
}

// ---------------- K1: recurrence + fc1/fc2 head (standalone, full regs) ----------
__global__ void __launch_bounds__(256) compute_kernel(
    const float* __restrict__ x,      const float* __restrict__ feat,
    const float* __restrict__ queues,
    const float* __restrict__ fc_h_w, const float* __restrict__ fc_h_b,
    const float* __restrict__ fc_c_w, const float* __restrict__ fc_c_b,
    const float* __restrict__ conv_b,
    const float* __restrict__ fc1_b,  const float* __restrict__ fc2_w,
    const float* __restrict__ fc2_b,
    float* __restrict__ out)
{
    int warp = threadIdx.x >> 5;
    int lane = threadIdx.x & 31;
    int b    = blockIdx.x * 8 + warp;

    float h, c;
    {
        float ha = fc_h_b[lane], ca = fc_c_b[lane];
        #pragma unroll
        for (int i = 0; i < 9; i++) {
            float wh = fc_h_w[lane * 9 + i];
            float wc = fc_c_w[lane * 9 + i];
            float v  = (i == 0) ? x[b] : feat[b * 8 + i - 1];
            ha += wh * v; ca += wc * v;
        }
        h = tanhf(ha); c = tanhf(ca);
    }
    g_hcol[(0 * BATCH + b) * RDIM + lane] = h;

    float y0 = 0.f, y1 = 0.f, y2 = 0.f, y3 = 0.f;
    float p = __ldg(queues + (size_t)((0 * BATCH + b) * RDIM + lane) * LQ + (LQ - 1));

    #pragma unroll 1
    for (int l = 0; l < NLAYERS; l++) {
        float pn = 0.f;
        if (l < NLAYERS - 1) {
            int dn = 1 << ((l + 1) & 7);
            pn = __ldg(queues + (size_t)(((l + 1) * BATCH + b) * RDIM + lane) * LQ + (LQ - dn));
        }

        float a0 = __ldg(conv_b + l * 128 +  0 + lane);
        float a1 = __ldg(conv_b + l * 128 + 32 + lane);
        float a2 = __ldg(conv_b + l * 128 + 64 + lane);
        float a3 = __ldg(conv_b + l * 128 + 96 + lane);

        const float2* wp = g_wT + l * 32 * 128;
        #pragma unroll 8
        for (int j = 0; j < 32; j++) {
            float pj = __shfl_sync(FULLMASK, p, j);
            float hj = __shfl_sync(FULLMASK, h, j);
            float2 w0 = wp[j * 128 +  0 + lane];
            float2 w1 = wp[j * 128 + 32 + lane];
            float2 w2 = wp[j * 128 + 64 + lane];
            float2 w3 = wp[j * 128 + 96 + lane];
            a0 += w0.x * pj + w0.y * hj;
            a1 += w1.x * pj + w1.y * hj;
            a2 += w2.x * pj + w2.y * hj;
            a3 += w3.x * pj + w3.y * hj;
        }
        c = sigf(a0) * c + tanhf(a1) * sigf(a2);
        h = sigf(a3) * tanhf(c);
        p = pn;

        if (l < NLAYERS - 1)
            g_hcol[((l + 1) * BATCH + b) * RDIM + lane] = h;

        const float* f1p = g_f1T + l * 32 * 128;
        #pragma unroll 8
        for (int j = 0; j < 32; j++) {
            float hj = __shfl_sync(FULLMASK, h, j);
            y0 += f1p[j * 128 +  0 + lane] * hj;
            y1 += f1p[j * 128 + 32 + lane] * hj;
            y2 += f1p[j * 128 + 64 + lane] * hj;
            y3 += f1p[j * 128 + 96 + lane] * hj;
        }
    }

    float sacc = fmaxf(y0 + fc1_b[ 0 + lane], 0.f) * fc2_w[ 0 + lane]
               + fmaxf(y1 + fc1_b[32 + lane], 0.f) * fc2_w[32 + lane]
               + fmaxf(y2 + fc1_b[64 + lane], 0.f) * fc2_w[64 + lane]
               + fmaxf(y3 + fc1_b[96 + lane], 0.f) * fc2_w[96 + lane];
    #pragma unroll
    for (int off = 16; off > 0; off >>= 1)
        sacc += __shfl_xor_sync(FULLMASK, sacc, off);
    if (lane == 0) out[b] = sacc + fc2_b[0];
}

// ---------------- K2: TMA bulk copy with 256->257 shift in smem ----------------
// chunk = 8 input rows (8KB dense) -> 8*257 floats out (8224B dense, 16B aligned)
__global__ void __launch_bounds__(256) copy_kernel(
    const float* __restrict__ queues, float* __restrict__ out)
{
    __shared__ __align__(16) float   s_in[2][2048];
    __shared__ __align__(16) float   s_out[2][2064];
    __shared__ float    s_h[8];
    __shared__ __align__(8) uint64_t s_mbar[2];

    const int tid = threadIdx.x;
    const int bid = blockIdx.x;
    const int grd = gridDim.x;

    unsigned mb0 = (unsigned)__cvta_generic_to_shared(&s_mbar[0]);
    unsigned mb1 = (unsigned)__cvta_generic_to_shared(&s_mbar[1]);

    if (tid == 0) {
        asm volatile("mbarrier.init.shared.b64 [%0], 1;" :: "r"(mb0) : "memory");
        asm volatile("mbarrier.init.shared.b64 [%0], 1;" :: "r"(mb1) : "memory");
        asm volatile("fence.proxy.async.shared::cta;" ::: "memory");
        // prologue: issue loads for it=0,1
        #pragma unroll
        for (int pi = 0; pi < 2; pi++) {
            long ch = bid + (long)pi * grd;
            if (ch < NCHUNKS) {
                unsigned mb = pi ? mb1 : mb0;
                unsigned dst = (unsigned)__cvta_generic_to_shared(&s_in[pi][0]);
                const float* src = queues + ch * 2048;
                asm volatile("mbarrier.arrive.expect_tx.shared.b64 _, [%0], %1;"
                             :: "r"(mb), "r"(8192) : "memory");
                asm volatile("cp.async.bulk.shared::cluster.global.mbarrier::complete_tx::bytes [%0], [%1], %2, [%3];"
                             :: "r"(dst), "l"(src), "r"(8192), "r"(mb) : "memory");
            }
        }
    }
    __syncthreads();

    int ph0 = 0, ph1 = 0;

    for (int it = 0; ; it++) {
        long chunk = bid + (long)it * grd;
        if (chunk >= NCHUNKS) break;
        int s = it & 1;
        unsigned mb = s ? mb1 : mb0;

        // prefetch h values for this chunk (issue early, completes under mbar wait)
        float hreg = 0.f;
        if (tid < 8) hreg = __ldg(g_hcol + chunk * 8 + tid);

        // ensure out[s] buffer's previous TMA store has finished reading smem
        if (tid == 0)
            asm volatile("cp.async.bulk.wait_group.read 1;" ::: "memory");

        // wait for load into in[s]
        {
            int ph = s ? ph1 : ph0;
            asm volatile(
                "{\n\t"
                ".reg .pred P;\n"
                "LW_%=:\n\t"
                "mbarrier.try_wait.parity.shared.b64 P, [%0], %1;\n\t"
                "@P bra LD_%=;\n\t"
                "bra LW_%=;\n"
                "LD_%=:\n\t"
                "}"
                :: "r"(mb), "r"(ph) : "memory");
            if (s) ph1 ^= 1; else ph0 ^= 1;
        }
        if (tid < 8) s_h[tid] = hreg;
        __syncthreads();

        // shuffle: 2056 out floats = 514 float4; e -> (g,r,t) in 2 groups of 4 rows
        const float* in   = s_in[s];
        float*       outb = s_out[s];
        for (int f = tid; f < 514; f += 256) {
            int e0 = 4 * f;
            float4 v;
            float* vp = (float*)&v;
            #pragma unroll
            for (int j = 0; j < 4; j++) {
                int ee = e0 + j;
                int g  = (ee >= 1028);
                int w  = ee - (g ? 1028 : 0);
                int r  = (w >= 257) + (w >= 514) + (w >= 771);
                int t  = w - 257 * r;
                int rc = g * 4 + r;
                vp[j] = (t < 256) ? in[rc * 256 + t] : s_h[rc];
            }
            *(float4*)(outb + e0) = v;
        }
        __syncthreads();

        if (tid == 0) {
            asm volatile("fence.proxy.async.shared::cta;" ::: "memory");
            unsigned src = (unsigned)__cvta_generic_to_shared(outb);
            float*   dst = out + 512 + chunk * 2056;
            asm volatile("cp.async.bulk.global.shared::cta.bulk_group [%0], [%1], %2;"
                         :: "l"(dst), "r"(src), "r"(8224) : "memory");
            asm volatile("cp.async.bulk.commit_group;" ::: "memory");
            // issue load for it+2 into in[s]
            long ch2 = chunk + 2L * grd;
            if (ch2 < NCHUNKS) {
                unsigned d2 = (unsigned)__cvta_generic_to_shared(&s_in[s][0]);
                const float* src2 = queues + ch2 * 2048;
                asm volatile("mbarrier.arrive.expect_tx.shared.b64 _, [%0], %1;"
                             :: "r"(mb), "r"(8192) : "memory");
                asm volatile("cp.async.bulk.shared::cluster.global.mbarrier::complete_tx::bytes [%0], [%1], %2, [%3];"
                             :: "r"(d2), "l"(src2), "r"(8192), "r"(mb) : "memory");
            }
        }
    }

    // drain outstanding TMA stores before exit
    if (tid == 0)
        asm volatile("cp.async.bulk.wait_group 0;" ::: "memory");
}

extern "C" void kernel_launch(void* const* d_in, const int* in_sizes, int n_in,
                              void* d_out, int out_size) {
    const float* x      = (const float*)d_in[0];
    const float* feat   = (const float*)d_in[1];
    const float* queues = (const float*)d_in[2];
    const float* fc_h_w = (const float*)d_in[3];
    const float* fc_h_b = (const float*)d_in[4];
    const float* fc_c_w = (const float*)d_in[5];
    const float* fc_c_b = (const float*)d_in[6];
    const float* conv_w = (const float*)d_in[7];
    const float* conv_b = (const float*)d_in[8];
    const float* fc1_w  = (const float*)d_in[9];
    const float* fc1_b  = (const float*)d_in[10];
    const float* fc2_w  = (const float*)d_in[11];
    const float* fc2_b  = (const float*)d_in[12];
    float* out = (float*)d_out;

    prep_kernel<<<(NLAYERS * 32 * 128 + 255) / 256, 256>>>(conv_w, fc1_w);
    compute_kernel<<<64, 256>>>(x, feat, queues,
                                fc_h_w, fc_h_b, fc_c_w, fc_c_b,
                                conv_b, fc1_b, fc2_w, fc2_b, out);
    copy_kernel<<<COPYGRID, 256>>>(queues, out);
}